// round 9
// baseline (speedup 1.0000x reference)
#include <cuda_runtime.h>

// ChunkedValueCrossAttn: softmax over a single context token == 1.0, so
// y[b,c,h,w] = (Wo @ (Wv @ context[b]))[c] + bo[c] — a constant per (b,c)
// broadcast over HxW. x/Wq/Wk are dead inputs.
//
// out: [2, 64, 1024, 1024] f32 = 536.9 MB write-only -> HBM store-bound.
//
// Two kernels + PDL: the const kernel (1 block) computes the 128 broadcast
// constants and triggers programmatic launch completion; the fill kernel
// (16384 blocks x 8 f4/thread — the measured-best store shape, DRAM 81%)
// launches concurrently under programmaticStreamSerialization and does
// cudaGridDependencySynchronize() before one uniform L2-hit g_const load.
// This keeps the fill prologue at ~1 wavefront / 0 barriers (vs round 8's
// 800-cycle per-block chain) while PDL hides the const kernel + node gap
// that cost 5.1us in round 2.

#define B_       2
#define CQ_      64
#define INNER_   32
#define CTX_     16
#define NCONST_  (B_ * CQ_)             // 128
#define TPB_     256
#define F4_PER_THREAD_ 8
#define F4_PER_BLOCK_  (TPB_ * F4_PER_THREAD_)   // 2048 float4 = 32KB

__device__ float g_const[NCONST_];

__global__ void compute_consts_kernel(const float* __restrict__ context,
                                      const float* __restrict__ Wv,
                                      const float* __restrict__ Wo,
                                      const float* __restrict__ bo) {
    __shared__ float s_v[B_][INNER_];   // v = context @ Wv^T  -> [B, inner]
    int tid = threadIdx.x;

    if (tid < B_ * INNER_) {
        int b = tid / INNER_;
        int o = tid % INNER_;
        float acc = 0.f;
        #pragma unroll
        for (int j = 0; j < CTX_; ++j)
            acc += Wv[o * CTX_ + j] * context[b * CTX_ + j];
        s_v[b][o] = acc;
    }
    __syncthreads();

    int b = tid / CQ_;
    int c = tid % CQ_;
    float acc = bo[c];
    #pragma unroll
    for (int o = 0; o < INNER_; ++o)
        acc += Wo[c * INNER_ + o] * s_v[b][o];
    g_const[tid] = acc;

    __threadfence();                    // publish g_const before trigger
    __syncthreads();                    // all 128 writes done
    if (tid == 0) cudaTriggerProgrammaticLaunchCompletion();
}

__global__ void __launch_bounds__(TPB_) fill_kernel(float4* __restrict__ out) {
    cudaGridDependencySynchronize();    // wait for g_const to be published
    float v = g_const[blockIdx.x >> 7]; // uniform per block, L2/L1 hit
    float4 f = make_float4(v, v, v, v);
    unsigned int base = blockIdx.x * (unsigned)F4_PER_BLOCK_ + threadIdx.x;
    #pragma unroll
    for (int k = 0; k < F4_PER_THREAD_; ++k)
        out[base + k * (unsigned)TPB_] = f;
}

extern "C" void kernel_launch(void* const* d_in, const int* in_sizes, int n_in,
                              void* d_out, int out_size) {
    // metadata order: x, context, Wq, Wk, Wv, Wo, bo
    const float* context = (const float*)d_in[1];
    const float* Wv      = (const float*)d_in[4];
    const float* Wo      = (const float*)d_in[5];
    const float* bo      = (const float*)d_in[6];

    compute_consts_kernel<<<1, NCONST_>>>(context, Wv, Wo, bo);

    // out_size = 134,217,728 floats = 33,554,432 float4 -> 16384 blocks exact
    int n4 = out_size / 4;
    int blocks = n4 / F4_PER_BLOCK_;    // 16384

    cudaLaunchConfig_t cfg = {};
    cfg.gridDim = dim3((unsigned)blocks);
    cfg.blockDim = dim3(TPB_);
    cfg.dynamicSmemBytes = 0;
    cfg.stream = 0;
    cudaLaunchAttribute attr[1];
    attr[0].id = cudaLaunchAttributeProgrammaticStreamSerialization;
    attr[0].val.programmaticStreamSerializationAllowed = 1;
    cfg.attrs = attr;
    cfg.numAttrs = 1;
    cudaLaunchKernelEx(&cfg, fill_kernel, (float4*)d_out);
}

// round 10
// speedup vs baseline: 1.0238x; 1.0238x over previous
#include <cuda_runtime.h>

// ChunkedValueCrossAttn: softmax over a single context token == 1.0, so
// y[b,c,h,w] = (Wo @ (Wv @ context[b]))[c] + bo[c] — a constant per (b,c)
// broadcast over HxW. x/Wq/Wk are dead inputs.
//
// out: [2, 64, 1024, 1024] f32 = 536.9 MB write-only -> HBM store-bound.
//
// Fused kernel, 16384 blocks x 32KB (the measured-best store shape; pure
// fill at this grid = 73.4us, DRAM 82%). TPB=128 so 8 blocks fit per SM
// (vs 4 at TPB=256): while one block's warps wait at the prologue barrier,
// 7 neighbors keep the store queue full (round 8's 1.7us prologue exposure
// should ~halve). Prologue itself is round 8's proven coalesced version:
// warp 0 loads Wv via 4x LDG.128 into padded shared, dot from LDS,
// 5-shfl butterfly, one STS + barrier.

#define B_       2
#define CQ_      64
#define INNER_   32
#define CTX_     16
#define TPB_     128
#define F4_PER_THREAD_ 16
#define F4_PER_BLOCK_  (TPB_ * F4_PER_THREAD_)   // 2048 float4 = 32KB

__global__ void __launch_bounds__(TPB_) fused_fill_kernel(
        float4* __restrict__ out,
        const float* __restrict__ context,
        const float* __restrict__ Wv,
        const float* __restrict__ Wo,
        const float* __restrict__ bo) {
    __shared__ float s_wv[INNER_][CTX_ + 1];   // 17-float rows: conflict-free
    __shared__ float s_ctx[CTX_];
    __shared__ float s_c;

    unsigned int slab = blockIdx.x >> 7;       // 128 blocks per slab
    unsigned int b = slab >> 6;                // batch index
    unsigned int c = slab & 63u;               // channel index

    if (threadIdx.x < 32) {
        int l = threadIdx.x;

        // Coalesced Wv load: 128 float4 total -> 4 LDG.128 per lane.
        const float4* Wv4 = (const float4*)Wv;
        #pragma unroll
        for (int t = 0; t < 4; ++t) {
            int idx = t * 32 + l;              // float4 index 0..127
            float4 w = Wv4[idx];
            float* dst = &s_wv[idx >> 2][(idx & 3) * 4];
            dst[0] = w.x; dst[1] = w.y; dst[2] = w.z; dst[3] = w.w;
        }
        if (l < CTX_) s_ctx[l] = context[b * CTX_ + l];
        float wo = Wo[c * INNER_ + l];         // coalesced 128B, 1 wavefront
        __syncwarp();

        // v_l = dot(Wv[l,:], ctx); LDS banks 17l+j -> conflict-free per j.
        float v = 0.f;
        #pragma unroll
        for (int j = 0; j < CTX_; ++j)
            v += s_wv[l][j] * s_ctx[j];

        float p = wo * v;
        #pragma unroll
        for (int off = 16; off > 0; off >>= 1)
            p += __shfl_xor_sync(0xFFFFFFFFu, p, off);
        if (l == 0) s_c = p + bo[c];
    }
    __syncthreads();

    float val = s_c;
    float4 f = make_float4(val, val, val, val);
    unsigned int base = blockIdx.x * (unsigned)F4_PER_BLOCK_ + threadIdx.x;
    #pragma unroll
    for (int k = 0; k < F4_PER_THREAD_; ++k)
        out[base + k * (unsigned)TPB_] = f;
}

extern "C" void kernel_launch(void* const* d_in, const int* in_sizes, int n_in,
                              void* d_out, int out_size) {
    // metadata order: x, context, Wq, Wk, Wv, Wo, bo
    const float* context = (const float*)d_in[1];
    const float* Wv      = (const float*)d_in[4];
    const float* Wo      = (const float*)d_in[5];
    const float* bo      = (const float*)d_in[6];

    // out_size = 134,217,728 floats = 33,554,432 float4 -> 16384 blocks exact
    int n4 = out_size / 4;
    int blocks = n4 / F4_PER_BLOCK_;   // 16384
    fused_fill_kernel<<<blocks, TPB_>>>((float4*)d_out, context, Wv, Wo, bo);
}

// round 11
// speedup vs baseline: 1.0299x; 1.0059x over previous
#include <cuda_runtime.h>

// ChunkedValueCrossAttn: softmax over a single context token == 1.0, so
// y[b,c,h,w] = (Wo @ (Wv @ context[b]))[c] + bo[c] — a constant per (b,c)
// broadcast over HxW. x/Wq/Wk are dead inputs.
//
// out: [2, 64, 1024, 1024] f32 = 536.9 MB write-only -> HBM store-bound.
//
// Fused, barrier-free, shared-free: EVERY warp computes its block's constant
// redundantly from fully COALESCED loads (4x LDG.128 Wv + 1x LDG.128 ctx +
// coalesced Wo + uniform bo ~ 9 L1 wavefronts/warp, all L1-hits after wave 1)
// and shuffle redistribution. No __syncthreads: each warp starts storing as
// soon as its own short chain resolves, overlapping with neighbor warps.
// Store shape is the measured-best: 16384 blocks x 256 thr x 8 f4/thread.
// (Rounds 4-5 proved scattered per-warp loads are fatal; this is the
// coalesced version of the same barrier-free idea.)

#define B_       2
#define CQ_      64
#define INNER_   32
#define CTX_     16
#define TPB_     256
#define F4_PER_THREAD_ 8
#define F4_PER_BLOCK_  (TPB_ * F4_PER_THREAD_)   // 2048 float4 = 32KB

__global__ void __launch_bounds__(TPB_) fused_fill_kernel(
        float4* __restrict__ out,
        const float* __restrict__ context,
        const float* __restrict__ Wv,
        const float* __restrict__ Wo,
        const float* __restrict__ bo) {
    unsigned int slab = blockIdx.x >> 7;       // 128 blocks per slab
    unsigned int b = slab >> 6;                // batch index
    unsigned int c = slab & 63u;               // channel index

    const unsigned FULL = 0xFFFFFFFFu;
    int l = threadIdx.x & 31;

    // ctx quarter for this lane: context[b] is 16 floats = 4 float4.
    float4 ctxq = ((const float4*)context)[b * 4 + (l & 3)];

    // Wv: 32 rows x 16 floats = 128 float4. Iteration t, lane l loads
    // float4 idx = 32t+l -> row 8t + l/4, quarter l&3. Coalesced 512B.
    const float4* Wv4 = (const float4*)Wv;
    float vpart[4];
    #pragma unroll
    for (int t = 0; t < 4; ++t) {
        float4 w = Wv4[t * 32 + l];
        float d = w.x * ctxq.x + w.y * ctxq.y + w.z * ctxq.z + w.w * ctxq.w;
        d += __shfl_xor_sync(FULL, d, 1);      // sum the 4 quarters of a row
        d += __shfl_xor_sync(FULL, d, 2);
        vpart[t] = d;                          // v_{8t + l/4}, replicated x4
    }

    float wo_l = Wo[c * INNER_ + l];           // lane l holds Wo[c,l], coalesced

    // p contribution from lanes with (l&3)==0: sum_t Wo[c, 8t+l/4]*v_{8t+l/4}
    float p = 0.f;
    #pragma unroll
    for (int t = 0; t < 4; ++t) {
        float woc = __shfl_sync(FULL, wo_l, 8 * t + (l >> 2));
        p += woc * vpart[t];
    }
    if (l & 3) p = 0.f;                        // each row counted once
    #pragma unroll
    for (int off = 16; off > 0; off >>= 1)
        p += __shfl_xor_sync(FULL, p, off);    // full sum in ALL lanes

    float val = p + bo[c];                     // uniform broadcast load

    float4 f = make_float4(val, val, val, val);
    unsigned int base = blockIdx.x * (unsigned)F4_PER_BLOCK_ + threadIdx.x;
    #pragma unroll
    for (int k = 0; k < F4_PER_THREAD_; ++k)
        out[base + k * (unsigned)TPB_] = f;
}

extern "C" void kernel_launch(void* const* d_in, const int* in_sizes, int n_in,
                              void* d_out, int out_size) {
    // metadata order: x, context, Wq, Wk, Wv, Wo, bo
    const float* context = (const float*)d_in[1];
    const float* Wv      = (const float*)d_in[4];
    const float* Wo      = (const float*)d_in[5];
    const float* bo      = (const float*)d_in[6];

    // out_size = 134,217,728 floats = 33,554,432 float4 -> 16384 blocks exact
    int n4 = out_size / 4;
    int blocks = n4 / F4_PER_BLOCK_;   // 16384
    fused_fill_kernel<<<blocks, TPB_>>>((float4*)d_out, context, Wv, Wo, bo);
}